// round 2
// baseline (speedup 1.0000x reference)
#include <cuda_runtime.h>
#include <cstdint>

// GHM-C loss:
//   loss = (1/n) * sum_b S_b / cnt_b            (tot cancels algebraically)
// bins over g = |sigmoid(pred) - onehot|; bce summed per bin.
// Main pass treats all elements as y=0; correction pass fixes the N target elems.

#define LOG2E 1.4426950408889634f
#define LN2 0.6931471805599453

__device__ double g_sum[10];        // per-bin sum of log2(1+e^x) terms (corrected)
__device__ unsigned int g_cnt[10];  // per-bin counts (corrected)

__device__ __forceinline__ float fex2(float x) {
    float y; asm("ex2.approx.f32 %0, %1;" : "=f"(y) : "f"(x)); return y;
}
__device__ __forceinline__ float flg2(float x) {
    float y; asm("lg2.approx.f32 %0, %1;" : "=f"(y) : "f"(x)); return y;
}
__device__ __forceinline__ float frcp(float x) {
    float y; asm("rcp.approx.f32 %0, %1;" : "=f"(y) : "f"(x)); return y;
}

// y=0 path: g = sigmoid(x), L = log2(1 + e^x)  (bce = L * ln2)
__device__ __forceinline__ void bin_and_L(float x, int& bi, float& L, float& g) {
    float e = fex2(x * LOG2E);
    float d = 1.0f + e;
    float r = frcp(d);
    g = e * r;
    L = flg2(d);
    int b = (int)(g * 10.0f);   // g >= 0; may hit 10 on rounding
    bi = b > 9 ? 9 : b;
}

__global__ void zero_kernel() {
    int t = threadIdx.x;
    if (t < 10) { g_sum[t] = 0.0; g_cnt[t] = 0u; }
}

// Main streaming histogram. Per-thread private bins in shared memory:
// for bin b: word [b*512 + tid] = count, [b*512 + 256 + tid] = f32 sum bits.
__global__ void __launch_bounds__(256) hist_kernel(const float* __restrict__ pred,
                                                   unsigned int nvec,
                                                   long long total) {
    __shared__ unsigned int s_hist[10 * 512];  // 20 KB
    const int tid = threadIdx.x;

#pragma unroll
    for (int b = 0; b < 10; b++) {
        s_hist[b * 512 + tid] = 0u;
        s_hist[b * 512 + 256 + tid] = 0u;
    }
    __syncthreads();

    const float4* __restrict__ p = (const float4*)pred;
    const unsigned int stride = gridDim.x * blockDim.x;
    const unsigned int gid = blockIdx.x * blockDim.x + tid;

    for (unsigned int i = gid; i < nvec; i += stride) {
        float4 v = p[i];
        float xs[4] = {v.x, v.y, v.z, v.w};
#pragma unroll
        for (int k = 0; k < 4; k++) {
            float g, L; int bi;
            bin_and_L(xs[k], bi, L, g);
            unsigned int base = (unsigned int)bi * 512u + (unsigned int)tid;
            s_hist[base] += 1u;
            float s = __uint_as_float(s_hist[base + 256]) + L;
            s_hist[base + 256] = __float_as_uint(s);
        }
    }

    // scalar tail (total not divisible by 4 — safe fallback)
    for (long long j = (long long)nvec * 4 + gid; j < total; j += stride) {
        float g, L; int bi;
        bin_and_L(pred[j], bi, L, g);
        unsigned int base = (unsigned int)bi * 512u + (unsigned int)tid;
        s_hist[base] += 1u;
        float s = __uint_as_float(s_hist[base + 256]) + L;
        s_hist[base + 256] = __float_as_uint(s);
    }
    __syncthreads();

    // block tree-reduce the 256 private histograms
    for (int off = 128; off > 0; off >>= 1) {
        if (tid < off) {
#pragma unroll
            for (int b = 0; b < 10; b++) {
                s_hist[b * 512 + tid] += s_hist[b * 512 + tid + off];
                float a = __uint_as_float(s_hist[b * 512 + 256 + tid]) +
                          __uint_as_float(s_hist[b * 512 + 256 + tid + off]);
                s_hist[b * 512 + 256 + tid] = __float_as_uint(a);
            }
        }
        __syncthreads();
    }

    if (tid < 10) {
        atomicAdd(&g_cnt[tid], s_hist[tid * 512]);
        atomicAdd(&g_sum[tid], (double)__uint_as_float(s_hist[tid * 512 + 256]));
    }
}

// Correction: element (i, target[i]) was counted as y=0. Subtract that
// contribution (bit-identical arithmetic) and add the y=1 one:
//   g1 = 1 - sigmoid(x),  bce1 = log(1+e^x) - x  -> L1 = L0 - x*log2e
// NOTE: target is int32 (JAX default x64-disabled aliases int64 -> int32).
__global__ void __launch_bounds__(256) corr_kernel(const float* __restrict__ pred,
                                                   const int* __restrict__ target,
                                                   int N, int C) {
    __shared__ float s_s[10];
    __shared__ int s_c[10];
    const int tid = threadIdx.x;
    if (tid < 10) { s_s[tid] = 0.0f; s_c[tid] = 0; }
    __syncthreads();

    int i = blockIdx.x * blockDim.x + tid;
    const int stride = gridDim.x * blockDim.x;
    for (; i < N; i += stride) {
        int t = target[i];
        if (t < 0) t = 0;
        if (t >= C) t = C - 1;   // defensive clamp; indices are valid in-range
        float x = pred[(long long)i * C + t];
        float g0, L0; int b0;
        bin_and_L(x, b0, L0, g0);   // must match main pass bit-for-bit

        float g1 = 1.0f - g0;
        int b1 = (int)(g1 * 10.0f);
        if (b1 > 9) b1 = 9;
        if (b1 < 0) b1 = 0;
        float L1 = L0 - x * LOG2E;

        atomicAdd(&s_c[b0], -1);
        atomicAdd(&s_s[b0], -L0);
        atomicAdd(&s_c[b1], 1);
        atomicAdd(&s_s[b1], L1);
    }
    __syncthreads();
    if (tid < 10) {
        atomicAdd(&g_cnt[tid], (unsigned int)s_c[tid]);  // wraps correctly for negatives
        atomicAdd(&g_sum[tid], (double)s_s[tid]);
    }
}

__global__ void final_kernel(float* __restrict__ out) {
    double acc = 0.0;
    int n = 0;
#pragma unroll
    for (int b = 0; b < 10; b++) {
        unsigned int c = g_cnt[b];
        if (c > 0u) { n++; acc += g_sum[b] / (double)c; }
    }
    if (n < 1) n = 1;
    out[0] = (float)(acc * LN2 / (double)n);
}

extern "C" void kernel_launch(void* const* d_in, const int* in_sizes, int n_in,
                              void* d_out, int out_size) {
    const float* pred = (const float*)d_in[0];
    const int* target = (const int*)d_in[1];
    long long total = (long long)in_sizes[0];
    int N = in_sizes[1];
    int C = (int)(total / N);
    unsigned int nvec = (unsigned int)(total >> 2);

    zero_kernel<<<1, 32>>>();

    // one full wave: ~8 blocks/SM * ~148 SMs
    int blocks = 1184;
    unsigned int needed = (nvec + 255u) / 256u;
    if ((unsigned int)blocks > needed) blocks = (int)needed;
    if (blocks < 1) blocks = 1;
    hist_kernel<<<blocks, 256>>>(pred, nvec, total);

    int cblocks = (N + 255) / 256;
    if (cblocks > 512) cblocks = 512;
    corr_kernel<<<cblocks, 256>>>(pred, target, N, C);

    final_kernel<<<1, 1>>>((float*)d_out);
}

// round 3
// speedup vs baseline: 1.1860x; 1.1860x over previous
#include <cuda_runtime.h>

// GHM-C loss, algebraically collapsed:
//   loss = (1/n) * sum_b S_b / cnt_b     (the `tot` factors cancel)
// over 10 bins of g = |sigmoid(pred) - onehot|, S_b = sum of bce terms.
// Main pass treats every element as y=0 (g = sigmoid(x), bce = ln(1+e^x));
// a correction pass fixes the N target elements with bit-identical arithmetic.
// bce is accumulated in log2 units and scaled by ln2 once at the end.

#define LOG2E 1.4426950408889634f
#define LN2 0.6931471805599453

__device__ double g_sum[10];   // per-bin sum of log2(1+e^x) (corrected)
__device__ double g_cnt[10];   // per-bin counts (exact integers in double)
__device__ int g_ticket;

__device__ __forceinline__ float fex2(float x) {
    float y; asm("ex2.approx.f32 %0, %1;" : "=f"(y) : "f"(x)); return y;
}
__device__ __forceinline__ float flg2(float x) {
    float y; asm("lg2.approx.f32 %0, %1;" : "=f"(y) : "f"(x)); return y;
}
__device__ __forceinline__ float frcp(float x) {
    float y; asm("rcp.approx.f32 %0, %1;" : "=f"(y) : "f"(x)); return y;
}

// floor(y) for y in [0, 16) without F2I (keeps the XU/MUFU pipe clear):
// round-down FADD against 2^23 leaves floor(y) in the low mantissa bits.
__device__ __forceinline__ int floor_bin(float y) {
    float f = __fadd_rd(y, 8388608.0f);          // FADD.RM, fma pipe
    int b = __float_as_int(f) & 0xFFFF;
    return b > 9 ? 9 : b;
}

// y=0 path: g = sigmoid(x), L = log2(1 + e^x). 3 XU ops total.
__device__ __forceinline__ void eval(float x, int& bi, float& L, float& g) {
    float e = fex2(x * LOG2E);
    float d = 1.0f + e;
    float r = frcp(d);
    g = e * r;
    L = flg2(d);
    bi = floor_bin(g * 10.0f);
}

__global__ void zero_kernel() {
    int t = threadIdx.x;
    if (t < 10) { g_sum[t] = 0.0; g_cnt[t] = 0.0; }
    if (t == 0) g_ticket = 0;
}

// Streaming histogram: per-thread private bins in shared as float2{sum, cnt}.
// One LDS.64 + one STS.64 per element. Layout [bin][tid] -> conflict-free.
__global__ void __launch_bounds__(256, 8)
hist_kernel(const float* __restrict__ pred, unsigned int nvec, long long total) {
    __shared__ float2 sh[10 * 256];   // 20 KB
    const int tid = threadIdx.x;

#pragma unroll
    for (int b = 0; b < 10; b++) sh[b * 256 + tid] = make_float2(0.f, 0.f);
    __syncthreads();

    const float4* __restrict__ p = (const float4*)pred;
    const unsigned int stride = gridDim.x * blockDim.x;

    for (unsigned int i = blockIdx.x * blockDim.x + tid; i < nvec; i += stride) {
        float4 v = p[i];
        float xs[4] = {v.x, v.y, v.z, v.w};
#pragma unroll
        for (int k = 0; k < 4; k++) {
            int bi; float L, g;
            eval(xs[k], bi, L, g);
            float2 a = sh[bi * 256 + tid];
            a.x += L; a.y += 1.0f;
            sh[bi * 256 + tid] = a;
        }
    }

    // scalar tail (total % 4 != 0 — not expected, but safe)
    for (long long j = (long long)nvec * 4 + blockIdx.x * blockDim.x + tid;
         j < total; j += stride) {
        int bi; float L, g;
        eval(pred[j], bi, L, g);
        float2 a = sh[bi * 256 + tid];
        a.x += L; a.y += 1.0f;
        sh[bi * 256 + tid] = a;
    }
    __syncthreads();

    for (int off = 128; off > 0; off >>= 1) {
        if (tid < off) {
#pragma unroll
            for (int b = 0; b < 10; b++) {
                float2 u = sh[b * 256 + tid];
                float2 w = sh[b * 256 + tid + off];
                sh[b * 256 + tid] = make_float2(u.x + w.x, u.y + w.y);
            }
        }
        __syncthreads();
    }

    if (tid < 10) {
        float2 t = sh[tid * 256];
        atomicAdd(&g_sum[tid], (double)t.x);
        atomicAdd(&g_cnt[tid], (double)t.y);
    }
}

// Correction for the N target elements (+ fused finalize in the last block).
//   subtract y=0 contribution (identical arithmetic), add y=1:
//   g1 = 1 - g0,  L1 = L0 - x*log2e
__global__ void __launch_bounds__(256)
corr_kernel(const float* __restrict__ pred, const int* __restrict__ target,
            int N, int C, float* __restrict__ out, int nblocks) {
    __shared__ float s_s[10];
    __shared__ int s_c[10];
    __shared__ int s_last;
    const int tid = threadIdx.x;
    if (tid < 10) { s_s[tid] = 0.0f; s_c[tid] = 0; }
    __syncthreads();

    const int stride = gridDim.x * blockDim.x;
    for (int i = blockIdx.x * blockDim.x + tid; i < N; i += stride) {
        int t = target[i];
        t = t < 0 ? 0 : (t >= C ? C - 1 : t);
        float x = pred[(long long)i * C + t];
        int b0; float L0, g0;
        eval(x, b0, L0, g0);                    // matches main pass bit-for-bit

        float g1 = fmaxf(1.0f - g0, 0.0f);
        int b1 = floor_bin(g1 * 10.0f);
        float L1 = L0 - x * LOG2E;

        atomicAdd(&s_c[b0], -1);
        atomicAdd(&s_s[b0], -L0);
        atomicAdd(&s_c[b1], 1);
        atomicAdd(&s_s[b1], L1);
    }
    __syncthreads();
    if (tid < 10) {
        atomicAdd(&g_cnt[tid], (double)s_c[tid]);
        atomicAdd(&g_sum[tid], (double)s_s[tid]);
    }
    __threadfence();
    if (tid == 0) s_last = (atomicAdd(&g_ticket, 1) == nblocks - 1) ? 1 : 0;
    __syncthreads();

    if (s_last && tid < 32) {
        double term = 0.0; int ne = 0;
        if (tid < 10) {
            double c = g_cnt[tid];
            if (c > 0.5) { term = g_sum[tid] / c; ne = 1; }
        }
#pragma unroll
        for (int o = 16; o > 0; o >>= 1) {
            term += __shfl_down_sync(0xffffffff, term, o);
            ne   += __shfl_down_sync(0xffffffff, ne, o);
        }
        if (tid == 0) {
            if (ne < 1) ne = 1;
            out[0] = (float)(term * LN2 / (double)ne);
        }
    }
}

extern "C" void kernel_launch(void* const* d_in, const int* in_sizes, int n_in,
                              void* d_out, int out_size) {
    const float* pred = (const float*)d_in[0];
    const int* target = (const int*)d_in[1];
    long long total = (long long)in_sizes[0];
    int N = in_sizes[1];
    int C = (int)(total / N);
    unsigned int nvec = (unsigned int)(total >> 2);

    zero_kernel<<<1, 32>>>();

    int blocks = 1184;   // 8 blocks x 148 SMs, single wave
    unsigned int needed = (nvec + 255u) / 256u;
    if ((unsigned int)blocks > needed) blocks = (int)needed;
    if (blocks < 1) blocks = 1;
    hist_kernel<<<blocks, 256>>>(pred, nvec, total);

    int cblocks = (N + 255) / 256;
    if (cblocks > 512) cblocks = 512;
    if (cblocks < 1) cblocks = 1;
    corr_kernel<<<cblocks, 256>>>(pred, target, N, C, (float*)d_out, cblocks);
}